// round 11
// baseline (speedup 1.0000x reference)
#include <cuda_runtime.h>
#include <math.h>

#define B 64
#define C 256
#define H 56
#define W 56
#define HW (H*W)
#define CHW (C*HW)

#define TW 8            // tile width (centers)
#define TH 14           // tile height (56/14 = 4 exact)
#define HALO_H (TH+8)   // 22
#define HPITCH 22       // halo row pitch (floats): 22r mod 32 has period 16 -> conflict-free
#define CCH 8           // channels per smem chunk (4 CTAs/SM)
#define NCHUNK (C/CCH)  // 32
#define THREADS 126     // 14 rows * 9 dy

#define SC_CH (TH*TW)         // 112 floats per channel (center)
#define SH_CH (HALO_H*HPITCH) // 484 floats per channel (halo)
#define BUF_FLOATS (CCH*(SC_CH+SH_CH))  // 4768
#define NPIX (TH*TW)          // 112
#define INPH_OFF (2*BUF_FLOATS)         // 9536 (> rbuf 9072, so rbuf aliases bufs)
#define SMEM_FLOATS (INPH_OFF + SH_CH)  // 10020 -> 40080 B

__device__ float g_inv_norm[B*HW];

typedef unsigned long long u64;

__device__ __forceinline__ void cpa16(unsigned dst, const float* src, int srcsz) {
    asm volatile("cp.async.cg.shared.global [%0], [%1], 16, %2;\n"
                 :: "r"(dst), "l"(src), "r"(srcsz));
}
__device__ __forceinline__ void cpa8(unsigned dst, const float* src, int srcsz) {
    asm volatile("cp.async.ca.shared.global [%0], [%1], 8, %2;\n"
                 :: "r"(dst), "l"(src), "r"(srcsz));
}
__device__ __forceinline__ void cpa_commit() {
    asm volatile("cp.async.commit_group;\n");
}
__device__ __forceinline__ u64 splat2(float v) {
    u64 r;
    asm("mov.b64 %0, {%1, %1};" : "=l"(r) : "f"(v));
    return r;
}
__device__ __forceinline__ void unpack2(u64 v, float& lo, float& hi) {
    asm("mov.b64 {%0, %1}, %2;" : "=f"(lo), "=f"(hi) : "l"(v));
}
__device__ __forceinline__ float lo_f(u64 v) { float a, b; unpack2(v, a, b); return a; }
__device__ __forceinline__ float hi_f(u64 v) { float a, b; unpack2(v, a, b); return b; }
__device__ __forceinline__ void ffma2(u64& acc, u64 a, u64 b) {
    asm("fma.rn.f32x2 %0, %1, %2, %0;" : "+l"(acc) : "l"(a), "l"(b));
}

// ---------------------------------------------------------------------------
// Pass 1: inv_norm. 4 threads per pixel-quad (64 channels each) + shfl reduce.
// (reverted to R9 layout: fully-coalesced 128B groups per warp)
// ---------------------------------------------------------------------------
__global__ void norm_kernel(const float* __restrict__ x) {
    int t    = blockIdx.x * blockDim.x + threadIdx.x;
    int unit = t >> 2;          // pixel-quad index
    int cg   = t & 3;           // channel group
    int b    = unit / (HW/4);
    int s4   = unit % (HW/4);
    const float4* px = (const float4*)(x + (size_t)b*CHW + (size_t)cg*64*HW) + s4;
    float a0=0.f, a1=0.f, a2=0.f, a3=0.f;
    #pragma unroll 16
    for (int c = 0; c < 64; c++) {
        float4 v = px[(size_t)c*(HW/4)];
        a0 = fmaf(v.x, v.x, a0);
        a1 = fmaf(v.y, v.y, a1);
        a2 = fmaf(v.z, v.z, a2);
        a3 = fmaf(v.w, v.w, a3);
    }
    a0 += __shfl_xor_sync(0xFFFFFFFFu, a0, 1);
    a1 += __shfl_xor_sync(0xFFFFFFFFu, a1, 1);
    a2 += __shfl_xor_sync(0xFFFFFFFFu, a2, 1);
    a3 += __shfl_xor_sync(0xFFFFFFFFu, a3, 1);
    a0 += __shfl_xor_sync(0xFFFFFFFFu, a0, 2);
    a1 += __shfl_xor_sync(0xFFFFFFFFu, a1, 2);
    a2 += __shfl_xor_sync(0xFFFFFFFFu, a2, 2);
    a3 += __shfl_xor_sync(0xFFFFFFFFu, a3, 2);
    if (cg == 0) {
        float4 r;
        r.x = 1.f / fmaxf(sqrtf(a0), 1e-12f);
        r.y = 1.f / fmaxf(sqrtf(a1), 1e-12f);
        r.z = 1.f / fmaxf(sqrtf(a2), 1e-12f);
        r.w = 1.f / fmaxf(sqrtf(a3), 1e-12f);
        ((float4*)g_inv_norm)[unit] = r;
    }
}

// ---------------------------------------------------------------------------
// Pass 2: raw correlation + argmax + gaussian soft-argmax.
// Grid (7,4,64), 126 threads, 4 CTAs/SM. Thread: dy=t%9, row=t/9.
// dx-pair FFMA2 mainloop; halo read as 8x LDS.64 (conflict-free, HPITCH=22).
// ---------------------------------------------------------------------------
__global__ __launch_bounds__(THREADS, 4)
void corr_kernel(const float* __restrict__ x, float* __restrict__ out) {
    const int tx0 = blockIdx.x * TW;
    const int ty0 = blockIdx.y * TH;
    const int b   = blockIdx.z;

    extern __shared__ float smem[];
    const int t = threadIdx.x;
    float* outp = out + (size_t)b * 3 * HW;

    if ((b & 7) == 0) {   // first frame of each segment: x_post == 0
        for (int i = t; i < NPIX; i += THREADS) {
            int o = (ty0 + i/TW)*W + tx0 + (i%TW);
            outp[o]        = 0.f;
            outp[HW + o]   = 0.f;
            outp[2*HW + o] = 0.f;
        }
        return;
    }

    const float* xc  = x + (size_t)b     * CHW;
    const float* xp  = x + (size_t)(b-1) * CHW;
    const float* inC = g_inv_norm + b     * HW;
    const float* inP = g_inv_norm + (b-1) * HW;

    unsigned smem_u32;
    { unsigned long long tmp;
      asm("cvta.to.shared.u64 %0, %1;" : "=l"(tmp) : "l"(smem));
      smem_u32 = (unsigned)tmp; }

    auto prefetch = [&](int chunk, int buf) {
        const int ch0 = chunk * CCH;
        unsigned bb = smem_u32 + buf * (BUF_FLOATS*4);
        // center: CCH*14*2 = 224 16B quads
        for (int i = t; i < CCH*TH*2; i += THREADS) {
            int c   = i / (TH*2);
            int rem = i - c*(TH*2);
            int r2  = rem >> 1;
            int lq  = (rem & 1) * 4;
            cpa16(bb + (c*SC_CH + r2*TW + lq)*4,
                  xc + (size_t)(ch0 + c)*HW + (ty0 + r2)*W + tx0 + lq, 16);
        }
        // halo: CCH*22*8 = 1408 8B pairs (pairs fully in or out: gx even)
        unsigned hb = bb + CCH*SC_CH*4;
        for (int i = t; i < CCH*HALO_H*8; i += THREADS) {
            int c   = i / (HALO_H*8);
            int rem = i - c*(HALO_H*8);
            int hy  = rem >> 3;
            int hx  = (rem & 7) * 2;
            int gy  = ty0 + hy - 4;
            int gx  = tx0 + hx - 4;
            bool in = (gy >= 0 && gy < H && gx >= 0 && gx < W);
            const float* src = in ? (xp + (size_t)(ch0 + c)*HW + gy*W + gx) : xp;
            cpa8(hb + (c*SH_CH + hy*HPITCH + hx)*4, src, in ? 8 : 0);
        }
        cpa_commit();
    };

    prefetch(0, 0);

    // stage inP halo tile once (postprocess only)
    float* inPh = smem + INPH_OFF;
    for (int i = t; i < SH_CH; i += THREADS) {
        int hy = i / HPITCH, hx = i - hy*HPITCH;
        int gy = ty0 + hy - 4, gx = tx0 + hx - 4;
        inPh[i] = (gy >= 0 && gy < H && gx >= 0 && gx < W && hx < 16)
                  ? inP[gy*W + gx] : 0.f;
    }

    const int dy  = t % 9;
    const int row = t / 9;        // 0..13

    // Per center i: 4 b64 accs (dx pairs) + 1 scalar.
    // even i: pairs (0,1)(2,3)(4,5)(6,7), scalar dx=8
    // odd  i: pairs (1,2)(3,4)(5,6)(7,8), scalar dx=0
    u64   acc2[32];
    float acc1[8];
    #pragma unroll
    for (int i = 0; i < 32; i++) acc2[i] = 0ull;
    #pragma unroll
    for (int i = 0; i < 8; i++) acc1[i] = 0.f;

    const int sc_off = row*TW;
    const int sh_off = (row + dy)*HPITCH;

    for (int k = 0; k < NCHUNK; k++) {
        if (k + 1 < NCHUNK) prefetch(k + 1, (k + 1) & 1);
        if (k + 1 < NCHUNK) asm volatile("cp.async.wait_group 1;\n");
        else                asm volatile("cp.async.wait_group 0;\n");
        __syncthreads();

        const float* bb  = smem + (k & 1) * BUF_FLOATS;
        const float* scb = bb + sc_off;
        const float* shb = bb + CCH*SC_CH + sh_off;
        #pragma unroll 2
        for (int c = 0; c < CCH; c++) {
            const float* scp = scb + c*SC_CH;
            const u64*   hrow = (const u64*)(shb + c*SH_CH);
            float4 v0 = *(const float4*)scp;
            float4 v1 = *(const float4*)(scp + 4);
            // halo as native b64 pairs via LDS.64 (conflict-free at pitch 22)
            u64 hp[8];
            #pragma unroll
            for (int q = 0; q < 8; q++) hp[q] = hrow[q];
            float v[8] = {v0.x, v0.y, v0.z, v0.w, v1.x, v1.y, v1.z, v1.w};

            #pragma unroll
            for (int i = 0; i < 8; i++) {
                u64 vs = splat2(v[i]);
                if ((i & 1) == 0) {
                    #pragma unroll
                    for (int p = 0; p < 4; p++)
                        ffma2(acc2[i*4 + p], vs, hp[i/2 + p]);
                    acc1[i] = fmaf(v[i], lo_f(hp[(i + 8) >> 1]), acc1[i]);  // h[i+8]
                } else {
                    #pragma unroll
                    for (int p = 0; p < 4; p++)
                        ffma2(acc2[i*4 + p], vs, hp[(i + 1)/2 + p]);
                    acc1[i] = fmaf(v[i], hi_f(hp[(i - 1) >> 1]), acc1[i]);  // h[i]
                }
            }
        }
        __syncthreads();
    }

    // dump raw accumulators to rbuf [112][81] (aliases buffers)
    {
        float* rb = smem;
        #pragma unroll
        for (int i = 0; i < 8; i++) {
            float* rp = rb + (row*TW + i)*81 + dy*9;
            if ((i & 1) == 0) {
                #pragma unroll
                for (int p = 0; p < 4; p++) {
                    float lo, hi;
                    unpack2(acc2[i*4 + p], lo, hi);
                    rp[2*p]     = lo;
                    rp[2*p + 1] = hi;
                }
                rp[8] = acc1[i];
            } else {
                #pragma unroll
                for (int p = 0; p < 4; p++) {
                    float lo, hi;
                    unpack2(acc2[i*4 + p], lo, hi);
                    rp[2*p + 1] = lo;
                    rp[2*p + 2] = hi;
                }
                rp[0] = acc1[i];
            }
        }
    }
    __syncthreads();

    // postprocess: one thread per pixel
    if (t < NPIX) {
        const float* r = smem + t*81;
        int ly = t / TW, lx = t % TW;
        const float* ph = inPh + ly*HPITCH + lx;
        float best = -INFINITY;
        int bi = 0;
        #pragma unroll
        for (int ky = 0; ky < 9; ky++)
            #pragma unroll
            for (int kx = 0; kx < 9; kx++) {
                float v = r[ky*9 + kx] * ph[ky*HPITCH + kx];
                if (v > best) { best = v; bi = ky*9 + kx; }
            }
        int biy = bi / 9, bix = bi - biy*9;
        float s = 0.f, sumh = 0.f, sumv = 0.f;
        #pragma unroll
        for (int ky = 0; ky < 9; ky++) {
            float ddy = (float)(ky - biy);
            float dy2 = ddy*ddy;
            #pragma unroll
            for (int kx = 0; kx < 9; kx++) {
                float ddx = (float)(kx - bix);
                float g = expf(-50.0f * (dy2 + ddx*ddx));   // 1/(2*0.1^2)
                float f = g * (r[ky*9 + kx] * ph[ky*HPITCH + kx]) * 10.0f;
                s    += f;
                sumh += f * (float)(ky - 4);
                sumv += f * (float)(kx - 4);
            }
        }
        s += 1e-12f;
        int o = (ty0 + ly)*W + tx0 + lx;
        float ic = inC[o];
        outp[o]        = sumh / s;
        outp[HW + o]   = sumv / s;
        outp[2*HW + o] = best * ic;   // conf = inC * max(raw*inP)
    }
}

// ---------------------------------------------------------------------------
extern "C" void kernel_launch(void* const* d_in, const int* in_sizes, int n_in,
                              void* d_out, int out_size) {
    const float* x = (const float*)d_in[0];
    float* out = (float*)d_out;

    norm_kernel<<<(B*HW) / 256, 256>>>(x);   // 4 threads per pixel-quad

    const int smem_bytes = SMEM_FLOATS * (int)sizeof(float);   // 40080
    cudaFuncSetAttribute(corr_kernel, cudaFuncAttributeMaxDynamicSharedMemorySize, smem_bytes);

    dim3 grid(W/TW, H/TH, B);   // (7, 4, 64)
    corr_kernel<<<grid, THREADS, smem_bytes>>>(x, out);
}

// round 12
// speedup vs baseline: 1.1750x; 1.1750x over previous
#include <cuda_runtime.h>
#include <math.h>

#define B 64
#define C 256
#define H 56
#define W 56
#define HW (H*W)
#define CHW (C*HW)

#define TW 8            // tile width (centers)
#define TH 14           // tile height (56/14 = 4 exact)
#define HALO_H (TH+8)   // 22
#define HPITCH 20       // halo row pitch (floats)
#define CCH 8           // channels per smem chunk
#define NCHUNK (C/CCH)  // 32
#define NBUF 3          // pipeline depth (enables single barrier per chunk)
#define THREADS 126     // 14 rows * 9 dy

#define SC_CH (TH*TW)         // 112 floats per channel (center)
#define SH_CH (HALO_H*HPITCH) // 440 floats per channel (halo)
#define BUF_FLOATS (CCH*(SC_CH+SH_CH))  // 4416
#define NPIX (TH*TW)          // 112
#define INPH_OFF (NBUF*BUF_FLOATS)      // 13248 (rbuf 9072 aliases buffers)
#define SMEM_FLOATS (INPH_OFF + SH_CH)  // 13688 -> 54752 B

__device__ float g_inv_norm[B*HW];

typedef unsigned long long u64;

__device__ __forceinline__ void cpa16(unsigned dst, const float* src, int srcsz) {
    asm volatile("cp.async.cg.shared.global [%0], [%1], 16, %2;\n"
                 :: "r"(dst), "l"(src), "r"(srcsz));
}
__device__ __forceinline__ void cpa_commit() {
    asm volatile("cp.async.commit_group;\n");
}
__device__ __forceinline__ u64 splat2(float v) {
    u64 r;
    asm("mov.b64 %0, {%1, %1};" : "=l"(r) : "f"(v));
    return r;
}
__device__ __forceinline__ void unpack2(u64 v, float& lo, float& hi) {
    asm("mov.b64 {%0, %1}, %2;" : "=f"(lo), "=f"(hi) : "l"(v));
}
__device__ __forceinline__ float lo_f(u64 v) { float a, b; unpack2(v, a, b); return a; }
__device__ __forceinline__ float hi_f(u64 v) { float a, b; unpack2(v, a, b); return b; }
__device__ __forceinline__ void ffma2(u64& acc, u64 a, u64 b) {
    asm("fma.rn.f32x2 %0, %1, %2, %0;" : "+l"(acc) : "l"(a), "l"(b));
}

// ---------------------------------------------------------------------------
// Pass 1: inv_norm. 4 threads per pixel-quad (64 channels each) + shfl reduce.
// ---------------------------------------------------------------------------
__global__ void norm_kernel(const float* __restrict__ x) {
    int t    = blockIdx.x * blockDim.x + threadIdx.x;
    int unit = t >> 2;          // pixel-quad index
    int cg   = t & 3;           // channel group
    int b    = unit / (HW/4);
    int s4   = unit % (HW/4);
    const float4* px = (const float4*)(x + (size_t)b*CHW + (size_t)cg*64*HW) + s4;
    float a0=0.f, a1=0.f, a2=0.f, a3=0.f;
    #pragma unroll 16
    for (int c = 0; c < 64; c++) {
        float4 v = px[(size_t)c*(HW/4)];
        a0 = fmaf(v.x, v.x, a0);
        a1 = fmaf(v.y, v.y, a1);
        a2 = fmaf(v.z, v.z, a2);
        a3 = fmaf(v.w, v.w, a3);
    }
    a0 += __shfl_xor_sync(0xFFFFFFFFu, a0, 1);
    a1 += __shfl_xor_sync(0xFFFFFFFFu, a1, 1);
    a2 += __shfl_xor_sync(0xFFFFFFFFu, a2, 1);
    a3 += __shfl_xor_sync(0xFFFFFFFFu, a3, 1);
    a0 += __shfl_xor_sync(0xFFFFFFFFu, a0, 2);
    a1 += __shfl_xor_sync(0xFFFFFFFFu, a1, 2);
    a2 += __shfl_xor_sync(0xFFFFFFFFu, a2, 2);
    a3 += __shfl_xor_sync(0xFFFFFFFFu, a3, 2);
    if (cg == 0) {
        float4 r;
        r.x = 1.f / fmaxf(sqrtf(a0), 1e-12f);
        r.y = 1.f / fmaxf(sqrtf(a1), 1e-12f);
        r.z = 1.f / fmaxf(sqrtf(a2), 1e-12f);
        r.w = 1.f / fmaxf(sqrtf(a3), 1e-12f);
        ((float4*)g_inv_norm)[unit] = r;
    }
}

// ---------------------------------------------------------------------------
// Pass 2: raw correlation + argmax + gaussian soft-argmax.
// Grid (7,4,64), 126 threads, 4 CTAs/SM. Thread: dy=t%9, row=t/9.
// dx-pair FFMA2 mainloop; 3-deep cp.async pipeline, ONE barrier per chunk.
// ---------------------------------------------------------------------------
__global__ __launch_bounds__(THREADS, 4)
void corr_kernel(const float* __restrict__ x, float* __restrict__ out) {
    const int tx0 = blockIdx.x * TW;
    const int ty0 = blockIdx.y * TH;
    const int b   = blockIdx.z;

    extern __shared__ float smem[];
    const int t = threadIdx.x;
    float* outp = out + (size_t)b * 3 * HW;

    if ((b & 7) == 0) {   // first frame of each segment: x_post == 0
        for (int i = t; i < NPIX; i += THREADS) {
            int o = (ty0 + i/TW)*W + tx0 + (i%TW);
            outp[o]        = 0.f;
            outp[HW + o]   = 0.f;
            outp[2*HW + o] = 0.f;
        }
        return;
    }

    const float* xc  = x + (size_t)b     * CHW;
    const float* xp  = x + (size_t)(b-1) * CHW;
    const float* inC = g_inv_norm + b     * HW;
    const float* inP = g_inv_norm + (b-1) * HW;

    unsigned smem_u32;
    { unsigned long long tmp;
      asm("cvta.to.shared.u64 %0, %1;" : "=l"(tmp) : "l"(smem));
      smem_u32 = (unsigned)tmp; }

    auto prefetch = [&](int chunk, int buf) {
        const int ch0 = chunk * CCH;
        unsigned bb = smem_u32 + buf * (BUF_FLOATS*4);
        // center: CCH*14*2 = 224 16B quads
        for (int i = t; i < CCH*TH*2; i += THREADS) {
            int c   = i / (TH*2);
            int rem = i - c*(TH*2);
            int r2  = rem >> 1;
            int lq  = (rem & 1) * 4;
            cpa16(bb + (c*SC_CH + r2*TW + lq)*4,
                  xc + (size_t)(ch0 + c)*HW + (ty0 + r2)*W + tx0 + lq, 16);
        }
        // halo: CCH*22*4 = 704 16B quads (quads fully in or out of bounds)
        unsigned hb = bb + CCH*SC_CH*4;
        for (int i = t; i < CCH*HALO_H*4; i += THREADS) {
            int c   = i / (HALO_H*4);
            int rem = i - c*(HALO_H*4);
            int hy  = rem >> 2;
            int hx  = (rem & 3) * 4;
            int gy  = ty0 + hy - 4;
            int gx  = tx0 + hx - 4;
            bool in = (gy >= 0 && gy < H && gx >= 0 && gx < W);
            const float* src = in ? (xp + (size_t)(ch0 + c)*HW + gy*W + gx) : xp;
            cpa16(hb + (c*SH_CH + hy*HPITCH + hx)*4, src, in ? 16 : 0);
        }
        cpa_commit();
    };

    prefetch(0, 0);
    prefetch(1, 1);

    // stage inP halo tile once (postprocess only)
    float* inPh = smem + INPH_OFF;
    for (int i = t; i < SH_CH; i += THREADS) {
        int hy = i / HPITCH, hx = i - hy*HPITCH;
        int gy = ty0 + hy - 4, gx = tx0 + hx - 4;
        inPh[i] = (gy >= 0 && gy < H && gx >= 0 && gx < W && hx < 16)
                  ? inP[gy*W + gx] : 0.f;
    }

    const int dy  = t % 9;
    const int row = t / 9;        // 0..13

    // Per center i: 4 b64 accs (dx pairs) + 1 scalar.
    // even i: pairs (0,1)(2,3)(4,5)(6,7), scalar dx=8
    // odd  i: pairs (1,2)(3,4)(5,6)(7,8), scalar dx=0
    u64   acc2[32];
    float acc1[8];
    #pragma unroll
    for (int i = 0; i < 32; i++) acc2[i] = 0ull;
    #pragma unroll
    for (int i = 0; i < 8; i++) acc1[i] = 0.f;

    const int sc_off = row*TW;
    const int sh_off = (row + dy)*HPITCH;

    int buf = 0;
    for (int k = 0; k < NCHUNK; k++) {
        // chunk k must be complete; allow 1 in-flight group (chunk k+1),
        // except on the last iteration where none may remain.
        if (k + 1 < NCHUNK) asm volatile("cp.async.wait_group 1;\n");
        else                asm volatile("cp.async.wait_group 0;\n");
        __syncthreads();
        // safe to refill buf (k+2)%3 == (k-1)%3: the sync above proved all
        // threads finished computing chunk k-1.
        if (k + 2 < NCHUNK) {
            int nb = buf + 2; if (nb >= NBUF) nb -= NBUF;
            prefetch(k + 2, nb);
        }

        const float* bb  = smem + buf * BUF_FLOATS;
        const float* scb = bb + sc_off;
        const float* shb = bb + CCH*SC_CH + sh_off;
        #pragma unroll 2
        for (int c = 0; c < CCH; c++) {
            const float* scp = scb + c*SC_CH;
            const float* shp = shb + c*SH_CH;
            float4 v0 = *(const float4*)scp;
            float4 v1 = *(const float4*)(scp + 4);
            // halo as native b64 pairs: hp[q] = (h[2q], h[2q+1]), q=0..7
            ulonglong2 q0 = *(const ulonglong2*)shp;
            ulonglong2 q1 = *(const ulonglong2*)(shp + 4);
            ulonglong2 q2 = *(const ulonglong2*)(shp + 8);
            ulonglong2 q3 = *(const ulonglong2*)(shp + 12);
            u64 hp[8] = {q0.x, q0.y, q1.x, q1.y, q2.x, q2.y, q3.x, q3.y};
            float v[8] = {v0.x, v0.y, v0.z, v0.w, v1.x, v1.y, v1.z, v1.w};

            #pragma unroll
            for (int i = 0; i < 8; i++) {
                u64 vs = splat2(v[i]);
                if ((i & 1) == 0) {
                    #pragma unroll
                    for (int p = 0; p < 4; p++)
                        ffma2(acc2[i*4 + p], vs, hp[i/2 + p]);
                    acc1[i] = fmaf(v[i], lo_f(hp[(i + 8) >> 1]), acc1[i]);  // h[i+8]
                } else {
                    #pragma unroll
                    for (int p = 0; p < 4; p++)
                        ffma2(acc2[i*4 + p], vs, hp[(i + 1)/2 + p]);
                    acc1[i] = fmaf(v[i], hi_f(hp[(i - 1) >> 1]), acc1[i]);  // h[i]
                }
            }
        }
        buf++; if (buf >= NBUF) buf = 0;
    }
    __syncthreads();   // all compute done before rbuf overwrites the buffers

    // dump raw accumulators to rbuf [112][81] (aliases buffers)
    {
        float* rb = smem;
        #pragma unroll
        for (int i = 0; i < 8; i++) {
            float* rp = rb + (row*TW + i)*81 + dy*9;
            if ((i & 1) == 0) {
                #pragma unroll
                for (int p = 0; p < 4; p++) {
                    float lo, hi;
                    unpack2(acc2[i*4 + p], lo, hi);
                    rp[2*p]     = lo;
                    rp[2*p + 1] = hi;
                }
                rp[8] = acc1[i];
            } else {
                #pragma unroll
                for (int p = 0; p < 4; p++) {
                    float lo, hi;
                    unpack2(acc2[i*4 + p], lo, hi);
                    rp[2*p + 1] = lo;
                    rp[2*p + 2] = hi;
                }
                rp[0] = acc1[i];
            }
        }
    }
    __syncthreads();

    // postprocess: one thread per pixel
    if (t < NPIX) {
        const float* r = smem + t*81;
        int ly = t / TW, lx = t % TW;
        const float* ph = inPh + ly*HPITCH + lx;
        float best = -INFINITY;
        int bi = 0;
        #pragma unroll
        for (int ky = 0; ky < 9; ky++)
            #pragma unroll
            for (int kx = 0; kx < 9; kx++) {
                float v = r[ky*9 + kx] * ph[ky*HPITCH + kx];
                if (v > best) { best = v; bi = ky*9 + kx; }
            }
        int biy = bi / 9, bix = bi - biy*9;
        float s = 0.f, sumh = 0.f, sumv = 0.f;
        #pragma unroll
        for (int ky = 0; ky < 9; ky++) {
            float ddy = (float)(ky - biy);
            float dy2 = ddy*ddy;
            #pragma unroll
            for (int kx = 0; kx < 9; kx++) {
                float ddx = (float)(kx - bix);
                float g = expf(-50.0f * (dy2 + ddx*ddx));   // 1/(2*0.1^2)
                float f = g * (r[ky*9 + kx] * ph[ky*HPITCH + kx]) * 10.0f;
                s    += f;
                sumh += f * (float)(ky - 4);
                sumv += f * (float)(kx - 4);
            }
        }
        s += 1e-12f;
        int o = (ty0 + ly)*W + tx0 + lx;
        float ic = inC[o];
        outp[o]        = sumh / s;
        outp[HW + o]   = sumv / s;
        outp[2*HW + o] = best * ic;   // conf = inC * max(raw*inP)
    }
}

// ---------------------------------------------------------------------------
extern "C" void kernel_launch(void* const* d_in, const int* in_sizes, int n_in,
                              void* d_out, int out_size) {
    const float* x = (const float*)d_in[0];
    float* out = (float*)d_out;

    norm_kernel<<<(B*HW) / 256, 256>>>(x);   // 4 threads per pixel-quad

    const int smem_bytes = SMEM_FLOATS * (int)sizeof(float);   // 54752
    cudaFuncSetAttribute(corr_kernel, cudaFuncAttributeMaxDynamicSharedMemorySize, smem_bytes);

    dim3 grid(W/TW, H/TH, B);   // (7, 4, 64)
    corr_kernel<<<grid, THREADS, smem_bytes>>>(x, out);
}